// round 6
// baseline (speedup 1.0000x reference)
#include <cuda_runtime.h>

#define TPB 256
#define STR 68   // padded row stride (floats) for the data region

// ---- packed f32x2 helpers ----
__device__ __forceinline__ unsigned long long pk2(float lo, float hi){
    unsigned long long r;
    asm("mov.b64 %0, {%1,%2};" : "=l"(r) : "f"(lo), "f"(hi));
    return r;
}
__device__ __forceinline__ unsigned long long fma2(unsigned long long a,
                                                   unsigned long long b,
                                                   unsigned long long c){
    unsigned long long d;
    asm("fma.rn.f32x2 %0, %1, %2, %3;" : "=l"(d) : "l"(a), "l"(b), "l"(c));
    return d;
}
__device__ __forceinline__ unsigned long long add2(unsigned long long a,
                                                   unsigned long long b){
    unsigned long long d;
    asm("add.rn.f32x2 %0, %1, %2;" : "=l"(d) : "l"(a), "l"(b));
    return d;
}
__device__ __forceinline__ float2 upk2(unsigned long long v){
    float2 f;
    asm("mov.b64 {%0,%1}, %2;" : "=f"(f.x), "=f"(f.y) : "l"(v));
    return f;
}

// shared memory float offsets
#define OFF_D 0
#define OFF_B 64
#define OFF_A 128                    // data region: X -> C -> Y -> P  (64 x STR)
#define OFF_W (OFF_A + 64*STR)       // weights [w][i][o], row stride 64
#define SMEM_FLOATS (OFF_W + 3*64*64)

extern "C" __global__ void __launch_bounds__(TPB, 3)
dct_conv_kernel(const float* __restrict__ x, const float* __restrict__ cw,
                const float* __restrict__ cb, float* __restrict__ out)
{
    extern __shared__ float sm[];
    float* sD = sm + OFF_D;
    float* sB = sm + OFF_B;
    float* sA = sm + OFF_A;
    float* sW = sm + OFF_W;

    const int tid = threadIdx.x;
    const int bid = blockIdx.x;
    const int b   = bid >> 10;
    const int pos = bid & 1023;
    const int bh  = pos >> 5;
    const int bw  = pos & 31;

    if (tid < 64){
        int k = tid >> 3, n = tid & 7;
        float v = 0.5f * cospif((float)((2*n+1)*k) * (1.0f/16.0f));
        if (k == 0) v *= 0.70710678118654752f;
        sD[tid] = v;
        sB[tid] = cb[tid];
    }
    // stage W transposed: sW[w][i][o], stride 64
    for (int g = tid; g < 64*64*3; g += TPB){
        int o = g / 192;
        int r = g - o*192;
        int i = r / 3;
        int w = r - i*3;
        sW[(w*64 + i)*64 + o] = cw[g];
    }

    // ---- load x block for all channels into sA ----
    const int ch = tid >> 2, q = tid & 3;
    const int k0 = q*2;
    {
        const float* gx = x + (((size_t)(b*64 + ch))*256 + (size_t)(bh*8))*256 + bw*8;
        #pragma unroll
        for (int rr = 0; rr < 2; rr++){
            int r = k0 + rr;
            float4 v0 = *(const float4*)(gx + r*256);
            float4 v1 = *(const float4*)(gx + r*256 + 4);
            float* d = sA + ch*STR + r*8;
            *(float4*)(d)   = v0;
            *(float4*)(d+4) = v1;
        }
    }
    __syncthreads();

    // ---- fused forward DCT: C = D * X * D^T, rows k0,k0+1 in registers ----
    float C0[8], C1[8];
    {
        float T0[8], T1[8];
        #pragma unroll
        for (int m=0;m<8;m++){ T0[m]=0.f; T1[m]=0.f; }
        #pragma unroll
        for (int n=0;n<8;n++){
            float4 x0 = *(const float4*)(sA + ch*STR + n*8);
            float4 x1 = *(const float4*)(sA + ch*STR + n*8 + 4);
            float xs[8] = {x0.x,x0.y,x0.z,x0.w,x1.x,x1.y,x1.z,x1.w};
            float d0 = sD[k0*8+n], d1 = sD[k0*8+8+n];
            #pragma unroll
            for (int m=0;m<8;m++){ T0[m] = fmaf(d0, xs[m], T0[m]);
                                   T1[m] = fmaf(d1, xs[m], T1[m]); }
        }
        #pragma unroll
        for (int l=0;l<8;l++){
            float4 d0v = *(const float4*)(sD + l*8);
            float4 d1v = *(const float4*)(sD + l*8 + 4);
            float ds[8] = {d0v.x,d0v.y,d0v.z,d0v.w,d1v.x,d1v.y,d1v.z,d1v.w};
            float s0=0.f, s1=0.f;
            #pragma unroll
            for (int m=0;m<8;m++){ s0 = fmaf(T0[m], ds[m], s0);
                                   s1 = fmaf(T1[m], ds[m], s1); }
            C0[l]=s0; C1[l]=s1;
        }
    }
    __syncthreads();   // all reads of X done -> safe to overwrite with C
    {
        float* cp = sA + ch*STR + k0*8;
        *(float4*)(cp)      = make_float4(C0[0],C0[1],C0[2],C0[3]);
        *(float4*)(cp+4)    = make_float4(C0[4],C0[5],C0[6],C0[7]);
        *(float4*)(cp+8)    = make_float4(C1[0],C1[1],C1[2],C1[3]);
        *(float4*)(cp+12)   = make_float4(C1[4],C1[5],C1[6],C1[7]);
        if (q == 3){
            float* zp = sA + ch*STR + 64;
            zp[0]=0.f; zp[1]=0.f; zp[2]=0.f; zp[3]=0.f;
        }
    }
    __syncthreads();

    // ---- conv: Y[o][t] = bias[o] + sum_{i,w} W[o,i,w] * C[i][t+w] ----
    // mapping: ih = lane bit0 (i-half), t3 = bits1-3, o4 = bits4-7
    const int ih = tid & 1;
    const int t3 = (tid >> 1) & 7;
    const int o4 = (tid >> 4) & 15;
    const int t0 = t3*8, o0 = o4*4;

    unsigned long long acc[2][8];
    #pragma unroll
    for (int p=0;p<2;p++)
        #pragma unroll
        for (int t=0;t<8;t++) acc[p][t] = 0ull;

    #pragma unroll 2
    for (int ii = 0; ii < 32; ii++){
        const int i = (ih << 5) + ii;
        const float* crow = sA + i*STR + t0;
        float4 c0 = *(const float4*)crow;
        float4 c1 = *(const float4*)(crow + 4);
        float c8 = crow[8], c9 = crow[9];
        unsigned long long cs[10];
        cs[0]=pk2(c0.x,c0.x); cs[1]=pk2(c0.y,c0.y); cs[2]=pk2(c0.z,c0.z); cs[3]=pk2(c0.w,c0.w);
        cs[4]=pk2(c1.x,c1.x); cs[5]=pk2(c1.y,c1.y); cs[6]=pk2(c1.z,c1.z); cs[7]=pk2(c1.w,c1.w);
        cs[8]=pk2(c8,c8);     cs[9]=pk2(c9,c9);
        #pragma unroll
        for (int w=0; w<3; w++){
            const float* wr = sW + (w*64 + i)*64 + o0;
            ulonglong2 wp = *(const ulonglong2*)wr;  // pairs (o0,o0+1),(o0+2,o0+3)
            #pragma unroll
            for (int tt=0; tt<8; tt++){
                acc[0][tt] = fma2(wp.x, cs[tt+w], acc[0][tt]);
                acc[1][tt] = fma2(wp.y, cs[tt+w], acc[1][tt]);
            }
        }
    }
    __syncthreads();   // all reads of C done -> region free for Y

    // ---- cross-half reduction via shfl.bfly(1), write Y ----
    {
        const int oA = o0 + 2*ih, oB = oA + 1;
        const float bA = sB[oA], bB = sB[oB];
        #pragma unroll
        for (int tt=0; tt<8; tt++){
            unsigned long long a0v = acc[0][tt], a1v = acc[1][tt];
            unsigned long long send = ih ? a0v : a1v;
            unsigned long long keep = ih ? a1v : a0v;
            unsigned long long recv = __shfl_xor_sync(0xFFFFFFFFu, send, 1);
            float2 s = upk2(add2(keep, recv));
            sA[oA*STR + t0 + tt] = s.x + bA;
            sA[oB*STR + t0 + tt] = s.y + bB;
        }
    }
    __syncthreads();

    // ---- inverse stage 1 in registers: P[k][m] = sum_l Y[k][l] D[l][m] ----
    {
        float4 y00 = *(const float4*)(sA + ch*STR + k0*8);
        float4 y01 = *(const float4*)(sA + ch*STR + k0*8 + 4);
        float4 y10 = *(const float4*)(sA + ch*STR + k0*8 + 8);
        float4 y11 = *(const float4*)(sA + ch*STR + k0*8 + 12);
        float y0[8] = {y00.x,y00.y,y00.z,y00.w,y01.x,y01.y,y01.z,y01.w};
        float y1[8] = {y10.x,y10.y,y10.z,y10.w,y11.x,y11.y,y11.z,y11.w};
        float P0[8], P1[8];
        #pragma unroll
        for (int m=0;m<8;m++){ P0[m]=0.f; P1[m]=0.f; }
        #pragma unroll
        for (int l=0;l<8;l++){
            float4 d0v = *(const float4*)(sD + l*8);
            float4 d1v = *(const float4*)(sD + l*8 + 4);
            float ds[8] = {d0v.x,d0v.y,d0v.z,d0v.w,d1v.x,d1v.y,d1v.z,d1v.w};
            float a = y0[l], bb = y1[l];
            #pragma unroll
            for (int m=0;m<8;m++){ P0[m] = fmaf(a,  ds[m], P0[m]);
                                   P1[m] = fmaf(bb, ds[m], P1[m]); }
        }
        // overwrite own Y rows with P rows (same-thread, no barrier needed)
        float* pp = sA + ch*STR + k0*8;
        *(float4*)(pp)    = make_float4(P0[0],P0[1],P0[2],P0[3]);
        *(float4*)(pp+4)  = make_float4(P0[4],P0[5],P0[6],P0[7]);
        *(float4*)(pp+8)  = make_float4(P1[0],P1[1],P1[2],P1[3]);
        *(float4*)(pp+12) = make_float4(P1[4],P1[5],P1[6],P1[7]);
    }
    __syncthreads();

    // ---- inverse stage 2: img[n][m] = sum_k D[k,n] P[k][m]; store ----
    {
        float a0[8], a1[8];
        #pragma unroll
        for (int m=0;m<8;m++){ a0[m]=0.f; a1[m]=0.f; }
        const int n0 = k0;
        #pragma unroll
        for (int k=0;k<8;k++){
            float4 p0 = *(const float4*)(sA + ch*STR + k*8);
            float4 p1 = *(const float4*)(sA + ch*STR + k*8 + 4);
            float ps[8] = {p0.x,p0.y,p0.z,p0.w,p1.x,p1.y,p1.z,p1.w};
            float d0 = sD[k*8 + n0], d1 = sD[k*8 + n0 + 1];
            #pragma unroll
            for (int m=0;m<8;m++){ a0[m] = fmaf(d0, ps[m], a0[m]);
                                   a1[m] = fmaf(d1, ps[m], a1[m]); }
        }
        float* go = out + (((size_t)(b*64 + ch))*256 + (size_t)(bh*8))*256 + bw*8;
        *(float4*)(go + n0*256)       = make_float4(a0[0],a0[1],a0[2],a0[3]);
        *(float4*)(go + n0*256 + 4)   = make_float4(a0[4],a0[5],a0[6],a0[7]);
        *(float4*)(go + (n0+1)*256)   = make_float4(a1[0],a1[1],a1[2],a1[3]);
        *(float4*)(go + (n0+1)*256+4) = make_float4(a1[4],a1[5],a1[6],a1[7]);
    }
}

extern "C" void kernel_launch(void* const* d_in, const int* in_sizes, int n_in,
                              void* d_out, int out_size)
{
    (void)in_sizes; (void)n_in; (void)out_size;
    const float* x  = (const float*)d_in[0];
    const float* cw = (const float*)d_in[1];
    const float* cb = (const float*)d_in[2];
    float* out = (float*)d_out;

    const size_t smem = (size_t)SMEM_FLOATS * sizeof(float);  // ~67 KB
    cudaFuncSetAttribute(dct_conv_kernel,
                         cudaFuncAttributeMaxDynamicSharedMemorySize, (int)smem);
    dct_conv_kernel<<<8192, TPB, smem>>>(x, cw, cb, out);
}